// round 2
// baseline (speedup 1.0000x reference)
#include <cuda_runtime.h>
#include <math.h>

#define HH 30
#define WWG 30
#define HW 900
#define DD 256
#define MAXO 16
#define BB 128
#define BPITCH 264   // 261 feature rows padded to 264 (float4-friendly)

// ---------------- device scratch (no allocations allowed) ----------------
__device__ float g_comb[BB * BPITCH * MAXO];   // [b][feat][k]  (transposed per batch)
__device__ float g_u[BB * DD];                 // W2 @ sn per batch
__device__ float g_q[BB * DD];                 // sn @ Wp per batch
__device__ float g_bdot[BB];                   // b2 . sn per batch
__device__ float g_E[DD * DD];                 // W2 @ Wp
__device__ float g_r[DD];                      // b2 @ Wp
__device__ int   g_valid[BB * MAXO];

// =========================================================================
// Kernel 1: per-batch connected components (min-index labels) + object
// extraction + bbox-pooled features written transposed to g_comb.
// =========================================================================
__global__ __launch_bounds__(256) void ccl_feat_kernel(const float* __restrict__ grid_emb,
                                                       const int* __restrict__ grid) {
    int b = blockIdx.x, tid = threadIdx.x;
    __shared__ int g[HW], lab[HW], slot_of[HW];
    __shared__ int s_changed, nvalid;
    __shared__ int robj[MAXO], rmin[MAXO], rmax[MAXO], cmin[MAXO], cmax[MAXO];

    for (int c = tid; c < HW; c += 256) {
        int v = grid[b * HW + c];
        g[c] = v;
        lab[c] = (v > 0) ? c : HW;
    }
    __syncthreads();

    // label propagation: neighbor-min + path compression, to fixed point
    for (int it = 0; it < 512; it++) {
        if (tid == 0) s_changed = 0;
        __syncthreads();
        for (int c = tid; c < HW; c += 256) {
            int gc = g[c];
            if (gc > 0) {
                int m = lab[c];
                int col = c % WWG;
                if (c >= WWG && g[c - WWG] == gc) { int t = lab[c - WWG]; if (t < m) m = t; }
                if (c < HW - WWG && g[c + WWG] == gc) { int t = lab[c + WWG]; if (t < m) m = t; }
                if (col > 0 && g[c - 1] == gc) { int t = lab[c - 1]; if (t < m) m = t; }
                if (col < WWG - 1 && g[c + 1] == gc) { int t = lab[c + 1]; if (t < m) m = t; }
                // bounded path compression (labels are monotone non-increasing)
                for (int hop = 0; hop < 32; hop++) {
                    int p = lab[m];
                    if (p >= m) break;
                    m = p;
                }
                if (m < lab[c]) { lab[c] = m; s_changed = 1; }
            }
        }
        __syncthreads();
        int ch = s_changed;
        __syncthreads();
        if (!ch) break;
    }

    for (int c = tid; c < HW; c += 256) slot_of[c] = -1;
    __syncthreads();
    if (tid == 0) {
        int cnt = 0;
        for (int c = 0; c < HW && cnt < MAXO; c++)
            if (g[c] > 0 && lab[c] == c) { slot_of[c] = cnt; robj[cnt] = c; cnt++; }
        nvalid = cnt;
    }
    __syncthreads();
    if (tid < MAXO) { rmin[tid] = HH; rmax[tid] = -1; cmin[tid] = WWG; cmax[tid] = -1; }
    __syncthreads();
    for (int c = tid; c < HW; c += 256) {
        if (g[c] > 0) {
            int s = slot_of[lab[c]];
            if (s >= 0) {
                int r = c / WWG, col = c % WWG;
                atomicMin(&rmin[s], r); atomicMax(&rmax[s], r);
                atomicMin(&cmin[s], col); atomicMax(&cmax[s], col);
            }
        }
    }
    __syncthreads();

    int nv = nvalid;
    float* cb = g_comb + (size_t)b * BPITCH * MAXO;
    for (int k = 0; k < MAXO; k++) {
        if (k < nv) {
            int y = rmin[k], x = cmin[k];
            int h = rmax[k] + 1 - y, w = cmax[k] + 1 - x;
            float s = 0.f;
            for (int i = y; i < y + h; i++) {
                const float* rowp = grid_emb + ((size_t)(b * HH + i) * WWG + x) * DD + tid;
                for (int j = 0; j < w; j++) s += rowp[j * DD];
            }
            cb[tid * MAXO + k] = s / (float)(h * w);
            if (tid < 5) {
                float v;
                int color = g[robj[k]];
                if (tid == 0)      v = (float)color * (1.0f / 9.0f);
                else if (tid == 1) v = (float)x * (1.0f / WWG);
                else if (tid == 2) v = (float)y * (1.0f / HH);
                else if (tid == 3) v = (float)w * (1.0f / WWG);
                else               v = (float)h * (1.0f / HH);
                cb[(DD + tid) * MAXO + k] = v;
            }
            if (tid == 0) g_valid[b * MAXO + k] = 1;
        } else {
            cb[tid * MAXO + k] = 0.f;
            if (tid < 8) cb[(DD + tid) * MAXO + k] = 0.f;
            if (tid == 0) g_valid[b * MAXO + k] = 0;
        }
    }
}

// =========================================================================
// Kernel 2: per-batch sn = normalize(mean(structure_rep)), u = W2@sn,
// q = sn@Wp, bdot = b2.sn
// =========================================================================
__global__ __launch_bounds__(256) void prep_kernel(const float* __restrict__ sr,
                                                   const float* __restrict__ W2,
                                                   const float* __restrict__ Wp,
                                                   const float* __restrict__ b2) {
    int b = blockIdx.x, tid = threadIdx.x;
    __shared__ float sn[DD];
    __shared__ float red[DD];
    const float* base = sr + (size_t)b * 8 * DD + tid;
    float s = 0.f;
#pragma unroll
    for (int j = 0; j < 8; j++) s += base[j * DD];
    s *= 0.125f;
    red[tid] = s * s; __syncthreads();
    for (int off = 128; off; off >>= 1) { if (tid < off) red[tid] += red[tid + off]; __syncthreads(); }
    float nrm = sqrtf(red[0]);
    float snv = s / fmaxf(nrm, 1e-8f);
    sn[tid] = snv;
    __syncthreads();
    red[tid] = snv * b2[tid]; __syncthreads();
    for (int off = 128; off; off >>= 1) { if (tid < off) red[tid] += red[tid + off]; __syncthreads(); }
    if (tid == 0) g_bdot[b] = red[0];

    // q[e] = sum_d sn[d] * Wp[d][e]   (coalesced over e = tid)
    float acc = 0.f;
    for (int d = 0; d < DD; d++) acc += sn[d] * Wp[d * DD + tid];
    g_q[b * DD + tid] = acc;

    // u[d] = sum_e W2[d][e] * sn[e]   (warp per row, coalesced)
    int wid = tid >> 5, lane = tid & 31;
    for (int d = wid; d < DD; d += 8) {
        float a = 0.f;
        const float* wr = W2 + d * DD;
        for (int e2 = lane; e2 < DD; e2 += 32) a += wr[e2] * sn[e2];
#pragma unroll
        for (int off = 16; off; off >>= 1) a += __shfl_down_sync(0xffffffffu, a, off);
        if (lane == 0) g_u[b * DD + d] = a;
    }
}

// =========================================================================
// Kernel 3: E = W2 @ Wp (64 blocks x 4 rows), r = b2 @ Wp (block 64)
// =========================================================================
__global__ __launch_bounds__(256) void ew_kernel(const float* __restrict__ W2,
                                                 const float* __restrict__ Wp,
                                                 const float* __restrict__ b2) {
    int br = blockIdx.x, e = threadIdx.x;
    if (br < 64) {
        __shared__ float w2s[4 * DD];
        int d0 = br * 4;
        for (int i = threadIdx.x; i < 4 * DD; i += 256) w2s[i] = W2[d0 * DD + i];
        __syncthreads();
        float a0 = 0.f, a1 = 0.f, a2 = 0.f, a3 = 0.f;
#pragma unroll 4
        for (int k = 0; k < DD; k++) {
            float wp = Wp[k * DD + e];
            a0 += w2s[0 * DD + k] * wp;
            a1 += w2s[1 * DD + k] * wp;
            a2 += w2s[2 * DD + k] * wp;
            a3 += w2s[3 * DD + k] * wp;
        }
        g_E[(d0 + 0) * DD + e] = a0;
        g_E[(d0 + 1) * DD + e] = a1;
        g_E[(d0 + 2) * DD + e] = a2;
        g_E[(d0 + 3) * DD + e] = a3;
    } else {
        float a = 0.f;
#pragma unroll 4
        for (int k = 0; k < DD; k++) a += b2[k] * Wp[k * DD + e];
        g_r[e] = a;
    }
}

// =========================================================================
// Kernel 4: fused MLP per batch: hidden = gelu(combined@W1+b1);
// pre = os*(hidden@E + r - dot*q) + bp  (invalid -> bp); layernorm.
// =========================================================================
__global__ __launch_bounds__(256) void mlp_kernel(const float* __restrict__ W1,
                                                  const float* __restrict__ b1,
                                                  const float* __restrict__ gamma,
                                                  const float* __restrict__ beta,
                                                  const float* __restrict__ bp,
                                                  const float* __restrict__ osp,
                                                  float* __restrict__ out) {
    int b = blockIdx.x, tid = threadIdx.x;
    int rg = tid >> 6, cg = tid & 63;
    int r0 = rg * 4, e0 = cg * 4;

    __shared__ float cs[BPITCH * MAXO];   // [k][r]
    __shared__ float hs[MAXO * DD];       // [r][e]
    __shared__ float u_s[DD], q_s[DD];
    __shared__ float red[1024], red2[1024];
    __shared__ float dots[MAXO], mur[MAXO], rstdr[MAXO];
    __shared__ int vld[MAXO];

    const float* cb = g_comb + (size_t)b * BPITCH * MAXO;
    for (int i = tid; i < (BPITCH * MAXO) / 4; i += 256)
        ((float4*)cs)[i] = ((const float4*)cb)[i];
    u_s[tid] = g_u[b * DD + tid];
    q_s[tid] = g_q[b * DD + tid];
    if (tid < MAXO) vld[tid] = g_valid[b * MAXO + tid];
    __syncthreads();

    float bdot = g_bdot[b];
    float os = osp[0];

    // ---- GEMM1: hidden = gelu(combined @ W1 + b1) ----
    float acc[4][4];
#pragma unroll
    for (int i = 0; i < 4; i++)
#pragma unroll
        for (int j = 0; j < 4; j++) acc[i][j] = 0.f;

#pragma unroll 4
    for (int k = 0; k < 261; k++) {
        float4 c4 = *(const float4*)&cs[k * MAXO + r0];
        float4 w4 = *(const float4*)&W1[k * DD + e0];
        float ca[4] = {c4.x, c4.y, c4.z, c4.w};
        float wa[4] = {w4.x, w4.y, w4.z, w4.w};
#pragma unroll
        for (int i = 0; i < 4; i++)
#pragma unroll
            for (int j = 0; j < 4; j++) acc[i][j] += ca[i] * wa[j];
    }

    float4 b14 = *(const float4*)&b1[e0];
    float bb[4] = {b14.x, b14.y, b14.z, b14.w};
    float h[4][4];
#pragma unroll
    for (int i = 0; i < 4; i++)
#pragma unroll
        for (int j = 0; j < 4; j++) {
            float xx = acc[i][j] + bb[j];
            h[i][j] = 0.5f * xx * (1.0f + erff(xx * 0.70710678118654752f));
        }
#pragma unroll
    for (int i = 0; i < 4; i++) {
        float4 v = make_float4(h[i][0], h[i][1], h[i][2], h[i][3]);
        *(float4*)&hs[(r0 + i) * DD + e0] = v;
    }

    // ---- dot[r] = hidden[r] . u + bdot ----
    float uu[4] = {u_s[e0], u_s[e0 + 1], u_s[e0 + 2], u_s[e0 + 3]};
#pragma unroll
    for (int i = 0; i < 4; i++)
        red[(r0 + i) * 64 + cg] = h[i][0] * uu[0] + h[i][1] * uu[1] + h[i][2] * uu[2] + h[i][3] * uu[3];
    __syncthreads();
    for (int off = 32; off; off >>= 1) {
        if (cg < off) {
#pragma unroll
            for (int i = 0; i < 4; i++)
                red[(r0 + i) * 64 + cg] += red[(r0 + i) * 64 + cg + off];
        }
        __syncthreads();
    }
    if (tid < MAXO) dots[tid] = red[tid * 64] + bdot;
    __syncthreads();

    // ---- GEMM2: hE = hidden @ E ----
    float a2[4][4];
#pragma unroll
    for (int i = 0; i < 4; i++)
#pragma unroll
        for (int j = 0; j < 4; j++) a2[i][j] = 0.f;

#pragma unroll 4
    for (int k = 0; k < DD; k++) {
        float4 E4 = *(const float4*)&g_E[k * DD + e0];
        float ee[4] = {E4.x, E4.y, E4.z, E4.w};
        float hv[4];
#pragma unroll
        for (int i = 0; i < 4; i++) hv[i] = hs[(r0 + i) * DD + k];
#pragma unroll
        for (int i = 0; i < 4; i++)
#pragma unroll
            for (int j = 0; j < 4; j++) a2[i][j] += hv[i] * ee[j];
    }

    // ---- epilogue: pre = os*(hE + r - dot*q) + bp ; invalid -> bp ----
    float4 bp4 = *(const float4*)&bp[e0];
    float4 rv4 = *(const float4*)&g_r[e0];
    float bpp[4] = {bp4.x, bp4.y, bp4.z, bp4.w};
    float rr[4] = {rv4.x, rv4.y, rv4.z, rv4.w};
    float qq[4] = {q_s[e0], q_s[e0 + 1], q_s[e0 + 2], q_s[e0 + 3]};
    float pre[4][4];
#pragma unroll
    for (int i = 0; i < 4; i++) {
        float dt = dots[r0 + i];
        int v = vld[r0 + i];
#pragma unroll
        for (int j = 0; j < 4; j++) {
            float p = os * (a2[i][j] + rr[j] - dt * qq[j]) + bpp[j];
            pre[i][j] = v ? p : bpp[j];
        }
    }

    // ---- layernorm ----
#pragma unroll
    for (int i = 0; i < 4; i++) {
        float s = pre[i][0] + pre[i][1] + pre[i][2] + pre[i][3];
        float sq = pre[i][0] * pre[i][0] + pre[i][1] * pre[i][1] +
                   pre[i][2] * pre[i][2] + pre[i][3] * pre[i][3];
        red[(r0 + i) * 64 + cg] = s;
        red2[(r0 + i) * 64 + cg] = sq;
    }
    __syncthreads();
    for (int off = 32; off; off >>= 1) {
        if (cg < off) {
#pragma unroll
            for (int i = 0; i < 4; i++) {
                red[(r0 + i) * 64 + cg] += red[(r0 + i) * 64 + cg + off];
                red2[(r0 + i) * 64 + cg] += red2[(r0 + i) * 64 + cg + off];
            }
        }
        __syncthreads();
    }
    if (tid < MAXO) {
        float m = red[tid * 64] * (1.0f / DD);
        mur[tid] = m;
        float va = red2[tid * 64] * (1.0f / DD) - m * m;
        rstdr[tid] = rsqrtf(va + 1e-5f);
    }
    __syncthreads();

    float4 g4 = *(const float4*)&gamma[e0];
    float4 be4 = *(const float4*)&beta[e0];
    float gg[4] = {g4.x, g4.y, g4.z, g4.w};
    float bee[4] = {be4.x, be4.y, be4.z, be4.w};
#pragma unroll
    for (int i = 0; i < 4; i++) {
        float m = mur[r0 + i], rs = rstdr[r0 + i];
        float4 o;
        o.x = (pre[i][0] - m) * rs * gg[0] + bee[0];
        o.y = (pre[i][1] - m) * rs * gg[1] + bee[1];
        o.z = (pre[i][2] - m) * rs * gg[2] + bee[2];
        o.w = (pre[i][3] - m) * rs * gg[3] + bee[3];
        *(float4*)&out[((size_t)(b * MAXO + r0 + i)) * DD + e0] = o;
    }
}

// =========================================================================
extern "C" void kernel_launch(void* const* d_in, const int* in_sizes, int n_in,
                              void* d_out, int out_size) {
    const float* grid_emb = (const float*)d_in[0];
    const int*   grid     = (const int*)d_in[1];
    const float* sr       = (const float*)d_in[2];
    const float* W1       = (const float*)d_in[3];
    const float* b1       = (const float*)d_in[4];
    const float* W2       = (const float*)d_in[5];
    const float* b2       = (const float*)d_in[6];
    const float* Wp       = (const float*)d_in[7];
    const float* bp       = (const float*)d_in[8];
    const float* gamma    = (const float*)d_in[9];
    const float* beta     = (const float*)d_in[10];
    const float* os       = (const float*)d_in[11];

    ccl_feat_kernel<<<BB, 256>>>(grid_emb, grid);
    prep_kernel<<<BB, 256>>>(sr, W2, Wp, b2);
    ew_kernel<<<65, 256>>>(W2, Wp, b2);
    mlp_kernel<<<BB, 256>>>(W1, b1, gamma, beta, bp, os, (float*)d_out);
}

// round 3
// speedup vs baseline: 1.4312x; 1.4312x over previous
#include <cuda_runtime.h>
#include <math.h>

#define HH 30
#define WWG 30
#define HW 900
#define DD 256
#define MAXO 16
#define BB 128
#define FPITCH 272   // 261 feature rows padded to 272 (17 K-tiles of 16)

// ---------------- device scratch (no allocations allowed) ----------------
__device__ __align__(16) float g_comb[BB * FPITCH * MAXO];  // [b][feat][k]
__device__ __align__(16) float g_u[BB * DD];                // W2 @ sn per batch
__device__ __align__(16) float g_q[BB * DD];                // sn @ Wp per batch
__device__ float g_bdot[BB];                                // b2 . sn per batch
__device__ __align__(16) float g_E[DD * DD];                // W2 @ Wp
__device__ __align__(16) float g_r[DD];                     // b2 @ Wp
__device__ __align__(16) float g_W1p[FPITCH * DD];          // W1 padded to 272 rows
__device__ int   g_valid[BB * MAXO];

// =========================================================================
// Kernel 1: per-batch CCL (min-index labels) + object extraction + pooled
// features written transposed ([feat][k]) to g_comb.
// =========================================================================
__global__ __launch_bounds__(256) void ccl_feat_kernel(const float* __restrict__ grid_emb,
                                                       const int* __restrict__ grid) {
    int b = blockIdx.x, tid = threadIdx.x;
    __shared__ int g[HW], lab[HW], slot_of[HW];
    __shared__ unsigned rootbits[32];
    __shared__ int wpre[32];
    __shared__ int s_changed, nvalid;
    __shared__ int robj[MAXO], rmin[MAXO], rmax[MAXO], cmin[MAXO], cmax[MAXO];

    for (int c = tid; c < HW; c += 256) {
        int v = grid[b * HW + c];
        g[c] = v;
        lab[c] = (v > 0) ? c : HW;
        slot_of[c] = -1;
    }
    if (tid < 32) rootbits[tid] = 0;
    __syncthreads();

    // label propagation: neighbor-min + bounded path compression, to fixed point
    for (int it = 0; it < 512; it++) {
        if (tid == 0) s_changed = 0;
        __syncthreads();
        for (int c = tid; c < HW; c += 256) {
            int gc = g[c];
            if (gc > 0) {
                int m = lab[c];
                int col = c % WWG;
                if (c >= WWG && g[c - WWG] == gc) { int t = lab[c - WWG]; if (t < m) m = t; }
                if (c < HW - WWG && g[c + WWG] == gc) { int t = lab[c + WWG]; if (t < m) m = t; }
                if (col > 0 && g[c - 1] == gc) { int t = lab[c - 1]; if (t < m) m = t; }
                if (col < WWG - 1 && g[c + 1] == gc) { int t = lab[c + 1]; if (t < m) m = t; }
                for (int hop = 0; hop < 32; hop++) {
                    int p = lab[m];
                    if (p >= m) break;
                    m = p;
                }
                if (m < lab[c]) { lab[c] = m; s_changed = 1; }
            }
        }
        __syncthreads();
        int ch = s_changed;
        __syncthreads();
        if (!ch) break;
    }

    // parallel root ranking: roots are cells with lab[c]==c; rank = #roots below
    for (int c = tid; c < HW; c += 256)
        if (g[c] > 0 && lab[c] == c) atomicOr(&rootbits[c >> 5], 1u << (c & 31));
    __syncthreads();
    if (tid == 0) {
        int s = 0;
        for (int w = 0; w < 29; w++) { wpre[w] = s; s += __popc(rootbits[w]); }
        nvalid = s < MAXO ? s : MAXO;
    }
    __syncthreads();
    for (int c = tid; c < HW; c += 256) {
        if (g[c] > 0 && lab[c] == c) {
            int w = c >> 5;
            int rank = wpre[w] + __popc(rootbits[w] & ((1u << (c & 31)) - 1u));
            if (rank < MAXO) { robj[rank] = c; slot_of[c] = rank; }
        }
    }
    if (tid < MAXO) { rmin[tid] = HH; rmax[tid] = -1; cmin[tid] = WWG; cmax[tid] = -1; }
    __syncthreads();
    for (int c = tid; c < HW; c += 256) {
        if (g[c] > 0) {
            int s = slot_of[lab[c]];
            if (s >= 0) {
                int r = c / WWG, col = c % WWG;
                atomicMin(&rmin[s], r); atomicMax(&rmax[s], r);
                atomicMin(&cmin[s], col); atomicMax(&cmax[s], col);
            }
        }
    }
    __syncthreads();

    int nv = nvalid;
    float* cb = g_comb + (size_t)b * FPITCH * MAXO;
    for (int i = tid; i < FPITCH * MAXO; i += 256) cb[i] = 0.f;
    if (tid < MAXO) g_valid[b * MAXO + tid] = (tid < nv) ? 1 : 0;
    __syncthreads();
    for (int k = 0; k < nv; k++) {
        int y = rmin[k], x = cmin[k];
        int h = rmax[k] + 1 - y, w = cmax[k] + 1 - x;
        float s = 0.f;
        for (int i = y; i < y + h; i++) {
            const float* rowp = grid_emb + ((size_t)(b * HH + i) * WWG + x) * DD + tid;
            for (int j = 0; j < w; j++) s += rowp[j * DD];
        }
        cb[tid * MAXO + k] = s / (float)(h * w);
        if (tid < 5) {
            float v;
            int color = g[robj[k]];
            if (tid == 0)      v = (float)color * (1.0f / 9.0f);
            else if (tid == 1) v = (float)x * (1.0f / WWG);
            else if (tid == 2) v = (float)y * (1.0f / HH);
            else if (tid == 3) v = (float)w * (1.0f / WWG);
            else               v = (float)h * (1.0f / HH);
            cb[(DD + tid) * MAXO + k] = v;
        }
    }
}

// =========================================================================
// Kernel 2: per-batch sn = normalize(mean(structure_rep)), u = W2@sn,
// q = sn@Wp, bdot = b2.sn
// =========================================================================
__global__ __launch_bounds__(256) void prep_kernel(const float* __restrict__ sr,
                                                   const float* __restrict__ W2,
                                                   const float* __restrict__ Wp,
                                                   const float* __restrict__ b2) {
    int b = blockIdx.x, tid = threadIdx.x;
    __shared__ float sn[DD];
    __shared__ float red[DD];
    const float* base = sr + (size_t)b * 8 * DD + tid;
    float s = 0.f;
#pragma unroll
    for (int j = 0; j < 8; j++) s += base[j * DD];
    s *= 0.125f;
    red[tid] = s * s; __syncthreads();
    for (int off = 128; off; off >>= 1) { if (tid < off) red[tid] += red[tid + off]; __syncthreads(); }
    float nrm = sqrtf(red[0]);
    float snv = s / fmaxf(nrm, 1e-8f);
    sn[tid] = snv;
    __syncthreads();
    red[tid] = snv * b2[tid]; __syncthreads();
    for (int off = 128; off; off >>= 1) { if (tid < off) red[tid] += red[tid + off]; __syncthreads(); }
    if (tid == 0) g_bdot[b] = red[0];

    float acc = 0.f;
#pragma unroll 8
    for (int d = 0; d < DD; d++) acc += sn[d] * Wp[d * DD + tid];
    g_q[b * DD + tid] = acc;

    int wid = tid >> 5, lane = tid & 31;
    for (int d = wid; d < DD; d += 8) {
        float a = 0.f;
        const float* wr = W2 + d * DD;
#pragma unroll 4
        for (int e2 = lane; e2 < DD; e2 += 32) a += wr[e2] * sn[e2];
#pragma unroll
        for (int off = 16; off; off >>= 1) a += __shfl_down_sync(0xffffffffu, a, off);
        if (lane == 0) g_u[b * DD + d] = a;
    }
}

// =========================================================================
// Kernel 3: E = W2@Wp (blocks 0..63), r = b2@Wp (block 64),
// W1 pad copy (blocks 65..132)
// =========================================================================
__global__ __launch_bounds__(256) void ew_kernel(const float* __restrict__ W2,
                                                 const float* __restrict__ Wp,
                                                 const float* __restrict__ b2,
                                                 const float* __restrict__ W1) {
    int br = blockIdx.x, e = threadIdx.x;
    if (br < 64) {
        __shared__ float w2s[4 * DD];
        int d0 = br * 4;
        for (int i = threadIdx.x; i < 4 * DD; i += 256) w2s[i] = W2[d0 * DD + i];
        __syncthreads();
        float a0 = 0.f, a1 = 0.f, a2 = 0.f, a3 = 0.f;
#pragma unroll 4
        for (int k = 0; k < DD; k++) {
            float wp = Wp[k * DD + e];
            a0 += w2s[0 * DD + k] * wp;
            a1 += w2s[1 * DD + k] * wp;
            a2 += w2s[2 * DD + k] * wp;
            a3 += w2s[3 * DD + k] * wp;
        }
        g_E[(d0 + 0) * DD + e] = a0;
        g_E[(d0 + 1) * DD + e] = a1;
        g_E[(d0 + 2) * DD + e] = a2;
        g_E[(d0 + 3) * DD + e] = a3;
    } else if (br == 64) {
        float a = 0.f;
#pragma unroll 4
        for (int k = 0; k < DD; k++) a += b2[k] * Wp[k * DD + e];
        g_r[e] = a;
    } else {
        // pad W1 (261x256) into g_W1p (272x256), zeros beyond
        int i = (br - 65) * 256 + e;            // float4 index, 0..17407
        const float4* w14 = (const float4*)W1;  // 261*64 = 16704 float4s
        float4* dst = (float4*)g_W1p;
        float4 v = make_float4(0.f, 0.f, 0.f, 0.f);
        if (i < 16704) v = w14[i];
        dst[i] = v;
    }
}

// =========================================================================
// Kernel 4: fused per-batch MLP with double-buffered smem weight tiles.
// hidden = gelu(comb@W1+b1); pre = os*(hidden@E + r - dot*q) + bp; layernorm.
// =========================================================================
__global__ __launch_bounds__(256) void mlp_kernel(const float* __restrict__ b1,
                                                  const float* __restrict__ gamma,
                                                  const float* __restrict__ beta,
                                                  const float* __restrict__ bp,
                                                  const float* __restrict__ osp,
                                                  float* __restrict__ out) {
    int b = blockIdx.x, tid = threadIdx.x;
    int rg = tid >> 6, cg = tid & 63;
    int r0 = rg * 4, e0 = cg * 4;

    extern __shared__ float sm[];
    float* csT  = sm;               // 272*16 = 4352
    float* wb0  = csT + 4352;       // 16*256 = 4096
    float* wb1  = wb0 + 4096;       // 4096
    float* hsT  = wb1 + 4096;       // 256*16 = 4096
    float* red  = hsT + 4096;       // 1024
    float* red2 = red + 1024;       // 1024
    float* u_s  = red2 + 1024;      // 256
    float* q_s  = u_s + 256;        // 256
    __shared__ float dots[MAXO], mur[MAXO], rstdr[MAXO];
    __shared__ int vld[MAXO];

    // stage combined (transposed) + per-batch vectors
    const float4* cb4 = (const float4*)(g_comb + (size_t)b * FPITCH * MAXO);
    for (int i = tid; i < (FPITCH * MAXO) / 4; i += 256)
        ((float4*)csT)[i] = cb4[i];
    u_s[tid] = g_u[b * DD + tid];
    q_s[tid] = g_q[b * DD + tid];
    if (tid < MAXO) vld[tid] = g_valid[b * MAXO + tid];

    const float4* w14 = (const float4*)g_W1p;  // 17 tiles of 1024 float4
    const float4* e4  = (const float4*)g_E;    // 16 tiles of 1024 float4

    // prologue: W1 tile 0 -> wb0
    {
        float4 pf[4];
#pragma unroll
        for (int j = 0; j < 4; j++) pf[j] = w14[tid + j * 256];
#pragma unroll
        for (int j = 0; j < 4; j++) ((float4*)wb0)[tid + j * 256] = pf[j];
    }
    __syncthreads();

    float bdot = g_bdot[b];
    float os = osp[0];

    // ---- GEMM1: hidden = gelu(comb @ W1 + b1), K = 272 in 17 tiles ----
    float acc[4][4];
#pragma unroll
    for (int i = 0; i < 4; i++)
#pragma unroll
        for (int j = 0; j < 4; j++) acc[i][j] = 0.f;

    for (int t = 0; t < 17; t++) {
        float4 pf[4];
        if (t < 16) {
            int base = (t + 1) * 1024;
#pragma unroll
            for (int j = 0; j < 4; j++) pf[j] = w14[base + tid + j * 256];
        }
        const float* wcur = (t & 1) ? wb1 : wb0;
#pragma unroll
        for (int kk = 0; kk < 16; kk++) {
            float4 c4 = *(const float4*)&csT[(t * 16 + kk) * MAXO + r0];
            float4 w4 = *(const float4*)&wcur[kk * 256 + e0];
            float ca[4] = {c4.x, c4.y, c4.z, c4.w};
            float wa[4] = {w4.x, w4.y, w4.z, w4.w};
#pragma unroll
            for (int i = 0; i < 4; i++)
#pragma unroll
                for (int j = 0; j < 4; j++) acc[i][j] += ca[i] * wa[j];
        }
        __syncthreads();
        if (t < 16) {
            float* wn = (t & 1) ? wb0 : wb1;
#pragma unroll
            for (int j = 0; j < 4; j++) ((float4*)wn)[tid + j * 256] = pf[j];
            __syncthreads();
        }
    }

    float4 b14 = *(const float4*)&b1[e0];
    float bb[4] = {b14.x, b14.y, b14.z, b14.w};
    float h[4][4];
#pragma unroll
    for (int i = 0; i < 4; i++)
#pragma unroll
        for (int j = 0; j < 4; j++) {
            float xx = acc[i][j] + bb[j];
            h[i][j] = 0.5f * xx * (1.0f + erff(xx * 0.70710678118654752f));
        }
    // store hidden transposed [e][r]
#pragma unroll
    for (int j = 0; j < 4; j++) {
        float4 v = make_float4(h[0][j], h[1][j], h[2][j], h[3][j]);
        *(float4*)&hsT[(e0 + j) * MAXO + r0] = v;
    }

    // ---- dot[r] = hidden[r] . u + bdot ----
    float uu[4] = {u_s[e0], u_s[e0 + 1], u_s[e0 + 2], u_s[e0 + 3]};
#pragma unroll
    for (int i = 0; i < 4; i++)
        red[(r0 + i) * 64 + cg] = h[i][0] * uu[0] + h[i][1] * uu[1] + h[i][2] * uu[2] + h[i][3] * uu[3];
    __syncthreads();
    for (int off = 32; off; off >>= 1) {
        if (cg < off) {
#pragma unroll
            for (int i = 0; i < 4; i++)
                red[(r0 + i) * 64 + cg] += red[(r0 + i) * 64 + cg + off];
        }
        __syncthreads();
    }
    if (tid < MAXO) dots[tid] = red[tid * 64] + bdot;

    // GEMM2 prologue: E tile 0 -> wb0 (safe: all reads of wb0 done)
    {
        float4 pf[4];
#pragma unroll
        for (int j = 0; j < 4; j++) pf[j] = e4[tid + j * 256];
#pragma unroll
        for (int j = 0; j < 4; j++) ((float4*)wb0)[tid + j * 256] = pf[j];
    }
    __syncthreads();

    // ---- GEMM2: hE = hidden @ E, K = 256 in 16 tiles ----
    float a2[4][4];
#pragma unroll
    for (int i = 0; i < 4; i++)
#pragma unroll
        for (int j = 0; j < 4; j++) a2[i][j] = 0.f;

    for (int t = 0; t < 16; t++) {
        float4 pf[4];
        if (t < 15) {
            int base = (t + 1) * 1024;
#pragma unroll
            for (int j = 0; j < 4; j++) pf[j] = e4[base + tid + j * 256];
        }
        const float* wcur = (t & 1) ? wb1 : wb0;
#pragma unroll
        for (int kk = 0; kk < 16; kk++) {
            float4 h4 = *(const float4*)&hsT[(t * 16 + kk) * MAXO + r0];
            float4 w4 = *(const float4*)&wcur[kk * 256 + e0];
            float ha[4] = {h4.x, h4.y, h4.z, h4.w};
            float wa[4] = {w4.x, w4.y, w4.z, w4.w};
#pragma unroll
            for (int i = 0; i < 4; i++)
#pragma unroll
                for (int j = 0; j < 4; j++) a2[i][j] += ha[i] * wa[j];
        }
        __syncthreads();
        if (t < 15) {
            float* wn = (t & 1) ? wb0 : wb1;
#pragma unroll
            for (int j = 0; j < 4; j++) ((float4*)wn)[tid + j * 256] = pf[j];
            __syncthreads();
        }
    }

    // ---- epilogue: pre = os*(hE + r - dot*q) + bp ; invalid -> bp ----
    float4 bp4 = *(const float4*)&bp[e0];
    float4 rv4 = *(const float4*)&g_r[e0];
    float bpp[4] = {bp4.x, bp4.y, bp4.z, bp4.w};
    float rr[4] = {rv4.x, rv4.y, rv4.z, rv4.w};
    float qq[4] = {q_s[e0], q_s[e0 + 1], q_s[e0 + 2], q_s[e0 + 3]};
    float pre[4][4];
#pragma unroll
    for (int i = 0; i < 4; i++) {
        float dt = dots[r0 + i];
        int v = vld[r0 + i];
#pragma unroll
        for (int j = 0; j < 4; j++) {
            float p = os * (a2[i][j] + rr[j] - dt * qq[j]) + bpp[j];
            pre[i][j] = v ? p : bpp[j];
        }
    }

    // ---- layernorm ----
#pragma unroll
    for (int i = 0; i < 4; i++) {
        float s = pre[i][0] + pre[i][1] + pre[i][2] + pre[i][3];
        float sq = pre[i][0] * pre[i][0] + pre[i][1] * pre[i][1] +
                   pre[i][2] * pre[i][2] + pre[i][3] * pre[i][3];
        red[(r0 + i) * 64 + cg] = s;
        red2[(r0 + i) * 64 + cg] = sq;
    }
    __syncthreads();
    for (int off = 32; off; off >>= 1) {
        if (cg < off) {
#pragma unroll
            for (int i = 0; i < 4; i++) {
                red[(r0 + i) * 64 + cg] += red[(r0 + i) * 64 + cg + off];
                red2[(r0 + i) * 64 + cg] += red2[(r0 + i) * 64 + cg + off];
            }
        }
        __syncthreads();
    }
    if (tid < MAXO) {
        float m = red[tid * 64] * (1.0f / DD);
        mur[tid] = m;
        float va = red2[tid * 64] * (1.0f / DD) - m * m;
        rstdr[tid] = rsqrtf(va + 1e-5f);
    }
    __syncthreads();

    float4 g4 = *(const float4*)&gamma[e0];
    float4 be4 = *(const float4*)&beta[e0];
    float gg[4] = {g4.x, g4.y, g4.z, g4.w};
    float bee[4] = {be4.x, be4.y, be4.z, be4.w};
#pragma unroll
    for (int i = 0; i < 4; i++) {
        float m = mur[r0 + i], rs = rstdr[r0 + i];
        float4 o;
        o.x = (pre[i][0] - m) * rs * gg[0] + bee[0];
        o.y = (pre[i][1] - m) * rs * gg[1] + bee[1];
        o.z = (pre[i][2] - m) * rs * gg[2] + bee[2];
        o.w = (pre[i][3] - m) * rs * gg[3] + bee[3];
        *(float4*)&out[((size_t)(b * MAXO + r0 + i)) * DD + e0] = o;
    }
}

#define MLP_SMEM ((4352 + 4096 + 4096 + 4096 + 1024 + 1024 + 256 + 256) * 4)

// =========================================================================
extern "C" void kernel_launch(void* const* d_in, const int* in_sizes, int n_in,
                              void* d_out, int out_size) {
    const float* grid_emb = (const float*)d_in[0];
    const int*   grid     = (const int*)d_in[1];
    const float* sr       = (const float*)d_in[2];
    const float* W1       = (const float*)d_in[3];
    const float* b1       = (const float*)d_in[4];
    const float* W2       = (const float*)d_in[5];
    const float* b2       = (const float*)d_in[6];
    const float* Wp       = (const float*)d_in[7];
    const float* bp       = (const float*)d_in[8];
    const float* gamma    = (const float*)d_in[9];
    const float* beta     = (const float*)d_in[10];
    const float* os       = (const float*)d_in[11];

    cudaFuncSetAttribute(mlp_kernel, cudaFuncAttributeMaxDynamicSharedMemorySize, MLP_SMEM);

    ccl_feat_kernel<<<BB, 256>>>(grid_emb, grid);
    prep_kernel<<<BB, 256>>>(sr, W2, Wp, b2);
    ew_kernel<<<133, 256>>>(W2, Wp, b2, W1);
    mlp_kernel<<<BB, 256, MLP_SMEM>>>(b1, gamma, beta, bp, os, (float*)d_out);
}

// round 4
// speedup vs baseline: 2.2410x; 1.5659x over previous
#include <cuda_runtime.h>
#include <math.h>

#define HH 30
#define WWG 30
#define HW 900
#define DD 256
#define MAXO 16
#define BB 128
#define FPITCH 288   // 261 feature rows padded to 288 (9 K-tiles of 32)

// ---------------- device scratch (no allocations allowed) ----------------
__device__ __align__(16) float g_comb[BB * FPITCH * MAXO];  // [b][feat][k]
__device__ __align__(16) float g_u[BB * DD];                // W2 @ sn per batch
__device__ __align__(16) float g_q[BB * DD];                // sn @ Wp per batch
__device__ float g_bdot[BB];                                // b2 . sn per batch
__device__ __align__(16) float g_E[DD * DD];                // W2 @ Wp
__device__ __align__(16) float g_r[DD];                     // b2 @ Wp
__device__ __align__(16) float g_W1p[FPITCH * DD];          // W1 padded to 288 rows
__device__ int   g_valid[BB * MAXO];

// =========================================================================
// Fused pre-kernel. blockIdx: [0,128) ccl+features, [128,256) prep,
// [256,320) E rows, 320 r, [321,393) W1 pad copy. All independent.
// =========================================================================
__global__ __launch_bounds__(256) void pre_kernel(const float* __restrict__ grid_emb,
                                                  const int* __restrict__ grid,
                                                  const float* __restrict__ sr,
                                                  const float* __restrict__ W1,
                                                  const float* __restrict__ W2,
                                                  const float* __restrict__ Wp,
                                                  const float* __restrict__ b2) {
    int br = blockIdx.x, tid = threadIdx.x;

    __shared__ int g[HW], lab[HW], slot_of[HW];
    __shared__ unsigned rootbits[32];
    __shared__ int wpre[32];
    __shared__ int s_changed, nvalid;
    __shared__ int robj[MAXO], rmin[MAXO], rmax[MAXO], cmin[MAXO], cmax[MAXO];
    __shared__ float sred[DD];   // prep: sn / reductions ; ew: W2 rows

    if (br < BB) {
        // ---------------- CCL + features ----------------
        int b = br;
        for (int c = tid; c < HW; c += 256) {
            int v = grid[b * HW + c];
            g[c] = v;
            lab[c] = (v > 0) ? c : HW;
            slot_of[c] = -1;
        }
        if (tid < 32) rootbits[tid] = 0;
        __syncthreads();

        for (int it = 0; it < 512; it++) {
            if (tid == 0) s_changed = 0;
            __syncthreads();
            for (int c = tid; c < HW; c += 256) {
                int gc = g[c];
                if (gc > 0) {
                    int m = lab[c];
                    int col = c % WWG;
                    if (c >= WWG && g[c - WWG] == gc) { int t = lab[c - WWG]; if (t < m) m = t; }
                    if (c < HW - WWG && g[c + WWG] == gc) { int t = lab[c + WWG]; if (t < m) m = t; }
                    if (col > 0 && g[c - 1] == gc) { int t = lab[c - 1]; if (t < m) m = t; }
                    if (col < WWG - 1 && g[c + 1] == gc) { int t = lab[c + 1]; if (t < m) m = t; }
                    for (int hop = 0; hop < 32; hop++) {
                        int p = lab[m];
                        if (p >= m) break;
                        m = p;
                    }
                    if (m < lab[c]) { lab[c] = m; s_changed = 1; }
                }
            }
            __syncthreads();
            int ch = s_changed;
            __syncthreads();
            if (!ch) break;
        }

        for (int c = tid; c < HW; c += 256)
            if (g[c] > 0 && lab[c] == c) atomicOr(&rootbits[c >> 5], 1u << (c & 31));
        __syncthreads();
        if (tid == 0) {
            int s = 0;
            for (int w = 0; w < 29; w++) { wpre[w] = s; s += __popc(rootbits[w]); }
            nvalid = s < MAXO ? s : MAXO;
        }
        __syncthreads();
        for (int c = tid; c < HW; c += 256) {
            if (g[c] > 0 && lab[c] == c) {
                int w = c >> 5;
                int rank = wpre[w] + __popc(rootbits[w] & ((1u << (c & 31)) - 1u));
                if (rank < MAXO) { robj[rank] = c; slot_of[c] = rank; }
            }
        }
        if (tid < MAXO) { rmin[tid] = HH; rmax[tid] = -1; cmin[tid] = WWG; cmax[tid] = -1; }
        __syncthreads();
        for (int c = tid; c < HW; c += 256) {
            if (g[c] > 0) {
                int s = slot_of[lab[c]];
                if (s >= 0) {
                    int r = c / WWG, col = c % WWG;
                    atomicMin(&rmin[s], r); atomicMax(&rmax[s], r);
                    atomicMin(&cmin[s], col); atomicMax(&cmax[s], col);
                }
            }
        }
        __syncthreads();

        int nv = nvalid;
        float* cb = g_comb + (size_t)b * FPITCH * MAXO;
        for (int i = tid; i < FPITCH * MAXO; i += 256) cb[i] = 0.f;
        if (tid < MAXO) g_valid[b * MAXO + tid] = (tid < nv) ? 1 : 0;
        __syncthreads();
        for (int k = 0; k < nv; k++) {
            int y = rmin[k], x = cmin[k];
            int h = rmax[k] + 1 - y, w = cmax[k] + 1 - x;
            float s = 0.f;
            for (int i = y; i < y + h; i++) {
                const float* rowp = grid_emb + ((size_t)(b * HH + i) * WWG + x) * DD + tid;
                for (int j = 0; j < w; j++) s += rowp[j * DD];
            }
            cb[tid * MAXO + k] = s / (float)(h * w);
            if (tid < 5) {
                float v;
                int color = g[robj[k]];
                if (tid == 0)      v = (float)color * (1.0f / 9.0f);
                else if (tid == 1) v = (float)x * (1.0f / WWG);
                else if (tid == 2) v = (float)y * (1.0f / HH);
                else if (tid == 3) v = (float)w * (1.0f / WWG);
                else               v = (float)h * (1.0f / HH);
                cb[(DD + tid) * MAXO + k] = v;
            }
        }
    } else if (br < 2 * BB) {
        // ---------------- prep: sn, u, q, bdot ----------------
        int b = br - BB;
        __shared__ float sn[DD];
        const float* base = sr + (size_t)b * 8 * DD + tid;
        float s = 0.f;
#pragma unroll
        for (int j = 0; j < 8; j++) s += base[j * DD];
        s *= 0.125f;
        sred[tid] = s * s; __syncthreads();
        for (int off = 128; off; off >>= 1) { if (tid < off) sred[tid] += sred[tid + off]; __syncthreads(); }
        float nrm = sqrtf(sred[0]);
        __syncthreads();
        float snv = s / fmaxf(nrm, 1e-8f);
        sn[tid] = snv;
        sred[tid] = snv * b2[tid]; __syncthreads();
        for (int off = 128; off; off >>= 1) { if (tid < off) sred[tid] += sred[tid + off]; __syncthreads(); }
        if (tid == 0) g_bdot[b] = sred[0];

        float acc = 0.f;
#pragma unroll 8
        for (int d = 0; d < DD; d++) acc += sn[d] * Wp[d * DD + tid];
        g_q[b * DD + tid] = acc;

        int wid = tid >> 5, lane = tid & 31;
        for (int d = wid; d < DD; d += 8) {
            float a = 0.f;
            const float* wr = W2 + d * DD;
#pragma unroll 4
            for (int e2 = lane; e2 < DD; e2 += 32) a += wr[e2] * sn[e2];
#pragma unroll
            for (int off = 16; off; off >>= 1) a += __shfl_down_sync(0xffffffffu, a, off);
            if (lane == 0) g_u[b * DD + d] = a;
        }
    } else if (br < 2 * BB + 64) {
        // ---------------- E = W2 @ Wp, 4 rows per block ----------------
        int d0 = (br - 2 * BB) * 4, e = tid;
        __shared__ float w2s[4 * DD];
        for (int i = tid; i < 4 * DD; i += 256) w2s[i] = W2[d0 * DD + i];
        __syncthreads();
        float a0 = 0.f, a1 = 0.f, a2 = 0.f, a3 = 0.f;
#pragma unroll 4
        for (int k = 0; k < DD; k++) {
            float wp = Wp[k * DD + e];
            a0 += w2s[0 * DD + k] * wp;
            a1 += w2s[1 * DD + k] * wp;
            a2 += w2s[2 * DD + k] * wp;
            a3 += w2s[3 * DD + k] * wp;
        }
        g_E[(d0 + 0) * DD + e] = a0;
        g_E[(d0 + 1) * DD + e] = a1;
        g_E[(d0 + 2) * DD + e] = a2;
        g_E[(d0 + 3) * DD + e] = a3;
    } else if (br == 2 * BB + 64) {
        // ---------------- r = b2 @ Wp ----------------
        float a = 0.f;
#pragma unroll 4
        for (int k = 0; k < DD; k++) a += b2[k] * Wp[k * DD + tid];
        g_r[tid] = a;
    } else {
        // ---------------- pad W1 (261x256) -> g_W1p (288x256) ----------------
        int i = (br - (2 * BB + 65)) * 256 + tid;   // float4 idx, 0..18431
        const float4* w14 = (const float4*)W1;      // 16704 real float4s
        float4 v = make_float4(0.f, 0.f, 0.f, 0.f);
        if (i < 16704) v = w14[i];
        ((float4*)g_W1p)[i] = v;
    }
}
#define PRE_GRID (2 * BB + 65 + 72)   // 393

// =========================================================================
// Kernel 2: fused per-batch MLP, double-buffered 32-row weight tiles.
// =========================================================================
__global__ __launch_bounds__(256) void mlp_kernel(const float* __restrict__ b1,
                                                  const float* __restrict__ gamma,
                                                  const float* __restrict__ beta,
                                                  const float* __restrict__ bp,
                                                  const float* __restrict__ osp,
                                                  float* __restrict__ out) {
    int b = blockIdx.x, tid = threadIdx.x;
    int rg = tid >> 6, cg = tid & 63;
    int r0 = rg * 4, e0 = cg * 4;
    int wid = tid >> 5, lane = tid & 31;

    extern __shared__ float sm[];
    float* csT  = sm;               // 288*16 = 4608
    float* wb0  = csT + 4608;       // 32*256 = 8192
    float* wb1  = wb0 + 8192;       // 8192
    float* hsT  = wb1 + 8192;       // 256*16 = 4096
    float* red  = hsT + 4096;       // 32
    float* red2 = red + 32;         // 32
    float* u_s  = red2 + 32;        // 256
    float* q_s  = u_s + 256;        // 256
    __shared__ float dots[MAXO], mur[MAXO], rstdr[MAXO];
    __shared__ int vld[MAXO];

    const float4* cb4 = (const float4*)(g_comb + (size_t)b * FPITCH * MAXO);
    for (int i = tid; i < (FPITCH * MAXO) / 4; i += 256)
        ((float4*)csT)[i] = cb4[i];
    u_s[tid] = g_u[b * DD + tid];
    q_s[tid] = g_q[b * DD + tid];
    if (tid < MAXO) vld[tid] = g_valid[b * MAXO + tid];

    const float4* w14 = (const float4*)g_W1p;  // 9 tiles of 2048 float4
    const float4* e4  = (const float4*)g_E;    // 8 tiles of 2048 float4

    // prologue: W1 tile 0 -> wb0 (8 float4 per thread)
    {
        float4 pf[8];
#pragma unroll
        for (int j = 0; j < 8; j++) pf[j] = w14[tid + j * 256];
#pragma unroll
        for (int j = 0; j < 8; j++) ((float4*)wb0)[tid + j * 256] = pf[j];
    }
    __syncthreads();

    float bdot = g_bdot[b];
    float os = osp[0];

    // ---- GEMM1: hidden = gelu(comb @ W1 + b1), K = 288 in 9 tiles of 32 ----
    float acc[4][4];
#pragma unroll
    for (int i = 0; i < 4; i++)
#pragma unroll
        for (int j = 0; j < 4; j++) acc[i][j] = 0.f;

    for (int t = 0; t < 9; t++) {
        float4 pf[8];
        if (t < 8) {
            int base = (t + 1) * 2048;
#pragma unroll
            for (int j = 0; j < 8; j++) pf[j] = w14[base + tid + j * 256];
        }
        const float* wcur = (t & 1) ? wb1 : wb0;
#pragma unroll
        for (int kk = 0; kk < 32; kk++) {
            float4 c4 = *(const float4*)&csT[(t * 32 + kk) * MAXO + r0];
            float4 w4 = *(const float4*)&wcur[kk * 256 + e0];
            float ca[4] = {c4.x, c4.y, c4.z, c4.w};
            float wa[4] = {w4.x, w4.y, w4.z, w4.w};
#pragma unroll
            for (int i = 0; i < 4; i++)
#pragma unroll
                for (int j = 0; j < 4; j++) acc[i][j] += ca[i] * wa[j];
        }
        __syncthreads();
        if (t < 8) {
            float* wn = (t & 1) ? wb0 : wb1;
#pragma unroll
            for (int j = 0; j < 8; j++) ((float4*)wn)[tid + j * 256] = pf[j];
            __syncthreads();
        }
    }

    float4 b14 = *(const float4*)&b1[e0];
    float bb[4] = {b14.x, b14.y, b14.z, b14.w};
    float h[4][4];
#pragma unroll
    for (int i = 0; i < 4; i++)
#pragma unroll
        for (int j = 0; j < 4; j++) {
            float xx = acc[i][j] + bb[j];
            h[i][j] = 0.5f * xx * (1.0f + erff(xx * 0.70710678118654752f));
        }
    // hidden transposed [e][r]
#pragma unroll
    for (int j = 0; j < 4; j++) {
        float4 v = make_float4(h[0][j], h[1][j], h[2][j], h[3][j]);
        *(float4*)&hsT[(e0 + j) * MAXO + r0] = v;
    }

    // ---- dot[r] = hidden[r].u + bdot : warp-shfl reduction ----
    float uu[4] = {u_s[e0], u_s[e0 + 1], u_s[e0 + 2], u_s[e0 + 3]};
    float p[4];
#pragma unroll
    for (int i = 0; i < 4; i++)
        p[i] = h[i][0] * uu[0] + h[i][1] * uu[1] + h[i][2] * uu[2] + h[i][3] * uu[3];
#pragma unroll
    for (int off = 16; off; off >>= 1)
#pragma unroll
        for (int i = 0; i < 4; i++) p[i] += __shfl_down_sync(0xffffffffu, p[i], off);
    if (lane == 0) {
#pragma unroll
        for (int i = 0; i < 4; i++) red[(r0 + i) * 2 + (wid & 1)] = p[i];
    }
    __syncthreads();
    if (tid < MAXO) dots[tid] = red[tid * 2] + red[tid * 2 + 1] + bdot;

    // GEMM2 prologue: E tile 0 -> wb0 (all GEMM1 reads done at last barrier)
    {
        float4 pf[8];
#pragma unroll
        for (int j = 0; j < 8; j++) pf[j] = e4[tid + j * 256];
#pragma unroll
        for (int j = 0; j < 8; j++) ((float4*)wb0)[tid + j * 256] = pf[j];
    }
    __syncthreads();

    // ---- GEMM2: hE = hidden @ E, K = 256 in 8 tiles of 32 ----
    float a2[4][4];
#pragma unroll
    for (int i = 0; i < 4; i++)
#pragma unroll
        for (int j = 0; j < 4; j++) a2[i][j] = 0.f;

    for (int t = 0; t < 8; t++) {
        float4 pf[8];
        if (t < 7) {
            int base = (t + 1) * 2048;
#pragma unroll
            for (int j = 0; j < 8; j++) pf[j] = e4[base + tid + j * 256];
        }
        const float* wcur = (t & 1) ? wb1 : wb0;
#pragma unroll
        for (int kk = 0; kk < 32; kk++) {
            float4 h4 = *(const float4*)&hsT[(t * 32 + kk) * MAXO + r0];
            float4 w4 = *(const float4*)&wcur[kk * 256 + e0];
            float ha[4] = {h4.x, h4.y, h4.z, h4.w};
            float wa[4] = {w4.x, w4.y, w4.z, w4.w};
#pragma unroll
            for (int i = 0; i < 4; i++)
#pragma unroll
                for (int j = 0; j < 4; j++) a2[i][j] += ha[i] * wa[j];
        }
        __syncthreads();
        if (t < 7) {
            float* wn = (t & 1) ? wb0 : wb1;
#pragma unroll
            for (int j = 0; j < 8; j++) ((float4*)wn)[tid + j * 256] = pf[j];
            __syncthreads();
        }
    }

    // ---- epilogue: pre = os*(hE + r - dot*q) + bp ; invalid -> bp ----
    float4 bp4 = *(const float4*)&bp[e0];
    float4 rv4 = *(const float4*)&g_r[e0];
    float bpp[4] = {bp4.x, bp4.y, bp4.z, bp4.w};
    float rr[4] = {rv4.x, rv4.y, rv4.z, rv4.w};
    float qq[4] = {q_s[e0], q_s[e0 + 1], q_s[e0 + 2], q_s[e0 + 3]};
    float pre[4][4];
#pragma unroll
    for (int i = 0; i < 4; i++) {
        float dt = dots[r0 + i];
        int v = vld[r0 + i];
#pragma unroll
        for (int j = 0; j < 4; j++) {
            float pv = os * (a2[i][j] + rr[j] - dt * qq[j]) + bpp[j];
            pre[i][j] = v ? pv : bpp[j];
        }
    }

    // ---- layernorm: warp-shfl reductions ----
    float ps[4], pq[4];
#pragma unroll
    for (int i = 0; i < 4; i++) {
        ps[i] = pre[i][0] + pre[i][1] + pre[i][2] + pre[i][3];
        pq[i] = pre[i][0] * pre[i][0] + pre[i][1] * pre[i][1] +
                pre[i][2] * pre[i][2] + pre[i][3] * pre[i][3];
    }
#pragma unroll
    for (int off = 16; off; off >>= 1)
#pragma unroll
        for (int i = 0; i < 4; i++) {
            ps[i] += __shfl_down_sync(0xffffffffu, ps[i], off);
            pq[i] += __shfl_down_sync(0xffffffffu, pq[i], off);
        }
    if (lane == 0) {
#pragma unroll
        for (int i = 0; i < 4; i++) {
            red[(r0 + i) * 2 + (wid & 1)] = ps[i];
            red2[(r0 + i) * 2 + (wid & 1)] = pq[i];
        }
    }
    __syncthreads();
    if (tid < MAXO) {
        float m = (red[tid * 2] + red[tid * 2 + 1]) * (1.0f / DD);
        mur[tid] = m;
        float va = (red2[tid * 2] + red2[tid * 2 + 1]) * (1.0f / DD) - m * m;
        rstdr[tid] = rsqrtf(va + 1e-5f);
    }
    __syncthreads();

    float4 g4 = *(const float4*)&gamma[e0];
    float4 be4 = *(const float4*)&beta[e0];
    float gg[4] = {g4.x, g4.y, g4.z, g4.w};
    float bee[4] = {be4.x, be4.y, be4.z, be4.w};
#pragma unroll
    for (int i = 0; i < 4; i++) {
        float m = mur[r0 + i], rs = rstdr[r0 + i];
        float4 o;
        o.x = (pre[i][0] - m) * rs * gg[0] + bee[0];
        o.y = (pre[i][1] - m) * rs * gg[1] + bee[1];
        o.z = (pre[i][2] - m) * rs * gg[2] + bee[2];
        o.w = (pre[i][3] - m) * rs * gg[3] + bee[3];
        *(float4*)&out[((size_t)(b * MAXO + r0 + i)) * DD + e0] = o;
    }
}

#define MLP_SMEM ((4608 + 8192 + 8192 + 4096 + 32 + 32 + 256 + 256) * 4)

// =========================================================================
extern "C" void kernel_launch(void* const* d_in, const int* in_sizes, int n_in,
                              void* d_out, int out_size) {
    const float* grid_emb = (const float*)d_in[0];
    const int*   grid     = (const int*)d_in[1];
    const float* sr       = (const float*)d_in[2];
    const float* W1       = (const float*)d_in[3];
    const float* b1       = (const float*)d_in[4];
    const float* W2       = (const float*)d_in[5];
    const float* b2       = (const float*)d_in[6];
    const float* Wp       = (const float*)d_in[7];
    const float* bp       = (const float*)d_in[8];
    const float* gamma    = (const float*)d_in[9];
    const float* beta     = (const float*)d_in[10];
    const float* os       = (const float*)d_in[11];

    cudaFuncSetAttribute(mlp_kernel, cudaFuncAttributeMaxDynamicSharedMemorySize, MLP_SMEM);

    pre_kernel<<<PRE_GRID, 256>>>(grid_emb, grid, sr, W1, W2, Wp, b2);
    mlp_kernel<<<BB, 256, MLP_SMEM>>>(b1, gamma, beta, bp, os, (float*)d_out);
}